// round 4
// baseline (speedup 1.0000x reference)
#include <cuda_runtime.h>
#include <cooperative_groups.h>
namespace cg = cooperative_groups;

#define NDIM 128
#define RPC  32          // rows per CTA (quarter)
#define BLK  128         // 128 threads: 8 row-groups x 16 col-groups, 4x8 per thread
#define CLUS 4

// shared-memory layout (float offsets)
#define OFF_W    0
#define OFF_Z    16384
#define OFF_A    32768          // 32x128 local quarter
#define OFF_X    36864          // 32x128 local quarter
#define OFF_XI   40960          // 128
#define OFF_PROB 41088          // 128
#define OFF_DINV 41216          // 128
#define SMEM_FLOATS 41344       // 165376 bytes

// ---------- packed f32x2 helpers ----------
__device__ __forceinline__ unsigned long long pack2(float v) {
    unsigned long long r;
    asm("mov.b64 %0, {%1, %1};" : "=l"(r) : "f"(v));
    return r;
}
__device__ __forceinline__ void fma2(unsigned long long& d, unsigned long long a, unsigned long long b) {
    asm("fma.rn.f32x2 %0, %1, %2, %0;" : "+l"(d) : "l"(a), "l"(b));
}
__device__ __forceinline__ float2 unpack2(unsigned long long v) {
    float2 r;
    asm("mov.b64 {%0, %1}, %2;" : "=f"(r.x), "=f"(r.y) : "l"(v));
    return r;
}
__device__ __forceinline__ float4 acc_lo(const unsigned long long* a, bool relu) {
    float2 p0 = unpack2(a[0]), p1 = unpack2(a[1]);
    float4 v = make_float4(p0.x, p0.y, p1.x, p1.y);
    if (relu) { v.x = fmaxf(v.x,0.f); v.y = fmaxf(v.y,0.f); v.z = fmaxf(v.z,0.f); v.w = fmaxf(v.w,0.f); }
    return v;
}
__device__ __forceinline__ float4 acc_hi(const unsigned long long* a, bool relu) {
    float2 p2 = unpack2(a[2]), p3 = unpack2(a[3]);
    float4 v = make_float4(p2.x, p2.y, p3.x, p3.y);
    if (relu) { v.x = fmaxf(v.x,0.f); v.y = fmaxf(v.y,0.f); v.z = fmaxf(v.z,0.f); v.w = fmaxf(v.w,0.f); }
    return v;
}

// ---------- 32x128x128 GEMM accumulate: each thread 4 rows x 8 cols ----------
// 128 threads = 8 row-groups x 16 col-groups. A loads broadcast within a
// row-group's lanes; B row loaded once per warp (4 warps) per k.
__device__ __forceinline__ void gemm32_acc(const float* __restrict__ As,
                                           const float* __restrict__ Bs,
                                           int tr, int tc,
                                           unsigned long long acc[4][4])
{
#pragma unroll
    for (int r = 0; r < 4; ++r)
#pragma unroll
        for (int c = 0; c < 4; ++c) acc[r][c] = 0ull;

#pragma unroll 2
    for (int k = 0; k < NDIM; k += 4) {
        float4 a[4];
#pragma unroll
        for (int r = 0; r < 4; ++r)
            a[r] = *(const float4*)(As + (tr + r) * NDIM + k);
#pragma unroll
        for (int kk = 0; kk < 4; ++kk) {
            const ulonglong2 b0 = *(const ulonglong2*)(Bs + (k + kk) * NDIM + tc);
            const ulonglong2 b1 = *(const ulonglong2*)(Bs + (k + kk) * NDIM + tc + 4);
#pragma unroll
            for (int r = 0; r < 4; ++r) {
                const unsigned long long p = pack2(((const float*)&a[r])[kk]);
                fma2(acc[r][0], p, b0.x);
                fma2(acc[r][1], p, b0.y);
                fma2(acc[r][2], p, b1.x);
                fma2(acc[r][3], p, b1.y);
            }
        }
    }
}

__global__ void __launch_bounds__(BLK, 1) __cluster_dims__(CLUS, 1, 1)
gcn_kernel(const float* __restrict__ xg, const float* __restrict__ Wg,
           float* __restrict__ outg)
{
    extern __shared__ float sm[];
    float* Ws   = sm + OFF_W;
    float* Z    = sm + OFF_Z;
    float* A    = sm + OFF_A;
    float* X    = sm + OFF_X;
    float* xi   = sm + OFF_XI;
    float* prob = sm + OFF_PROB;
    float* dinv = sm + OFF_DINV;

    cg::cluster_group cl = cg::this_cluster();
    const int rank  = (int)cl.block_rank();
    const int tid   = threadIdx.x;
    const int batch = blockIdx.x / CLUS;
    const int r0    = rank * RPC;
    const int tr    = (tid >> 4) << 2;   // local row base (0..28)
    const int tc    = (tid & 15) << 3;   // col base (0..120)

    float* peer[CLUS];
#pragma unroll
    for (int r = 0; r < CLUS; ++r) peer[r] = (float*)cl.map_shared_rank((void*)sm, r);

    const float* __restrict__ xb = xg + (size_t)batch * 16384 + (size_t)r0 * NDIM;
    float* __restrict__ ob = outg + (size_t)batch * 16384;

    // ---- prologue: W -> smem, local x quarter -> Z (temp), out quarter = eye ----
    for (int idx = tid; idx < 4096; idx += BLK)
        ((float4*)Ws)[idx] = ((const float4*)Wg)[idx];
    for (int idx = tid; idx < 1024; idx += BLK)
        ((float4*)Z)[idx] = ((const float4*)xb)[idx];
    for (int idx = tid; idx < 1024; idx += BLK) {
        const int lin = idx << 2;
        const int jg = r0 + (lin >> 7), c = lin & 127;
        float4 e = make_float4(0.f, 0.f, 0.f, 0.f);
        const int d = jg - c;
        if (d >= 0 && d < 4) ((float*)&e)[d] = 1.0f;
        ((float4*)(ob + (size_t)r0 * NDIM))[idx] = e;
        ((float4*)A)[idx] = e;    // A_local = eye quarter
    }
    __syncthreads();

    // X_local = relu(x_local @ W)
    {
        unsigned long long acc[4][4];
        gemm32_acc(Z, Ws, tr, tc, acc);
#pragma unroll
        for (int r = 0; r < 4; ++r) {
            *(float4*)(X + (tr + r) * NDIM + tc)     = acc_lo(acc[r], true);
            *(float4*)(X + (tr + r) * NDIM + tc + 4) = acc_hi(acc[r], true);
        }
    }
    __syncthreads();

    // broadcast X row 1 (owner: rank 0) for the first iteration
    if (rank == 0 && tid < 32) {
        const float4 v = ((const float4*)(X + 1 * NDIM))[tid];
#pragma unroll
        for (int r = 0; r < CLUS; ++r)
            ((float4*)(peer[r] + OFF_XI))[tid] = v;
    }
    cl.sync();

    for (int i = 1; i < NDIM; ++i) {
        // ---- prob[j] = dot(X_local[j], xi) for local j; broadcast to all ----
        {
            const int jl = tid >> 2, p = tid & 3;
            const float4* xj = (const float4*)(X + jl * NDIM) + (p << 3);
            const float4* xv = (const float4*)xi + (p << 3);
            float s = 0.f;
#pragma unroll
            for (int q = 0; q < 8; ++q) {
                const float4 u = xj[q], w = xv[q];
                s += u.x * w.x + u.y * w.y + u.z * w.z + u.w * w.w;
            }
            s += __shfl_down_sync(0xffffffffu, s, 2);
            s += __shfl_down_sync(0xffffffffu, s, 1);
            if (p == 0) {
                const int jg = r0 + jl;
#pragma unroll
                for (int r = 0; r < CLUS; ++r)
                    peer[r][OFF_PROB + jg] = s;
            }
        }

        // ---- Z quarter = X_local @ W, scattered to every CTA's full Z ----
        if (i < NDIM - 1) {
            unsigned long long acc[4][4];
            gemm32_acc(X, Ws, tr, tc, acc);
#pragma unroll
            for (int r = 0; r < 4; ++r) {
                const float4 vlo = acc_lo(acc[r], false);
                const float4 vhi = acc_hi(acc[r], false);
                const int gofs = (r0 + tr + r) * NDIM + tc;
#pragma unroll
                for (int q = 0; q < CLUS; ++q) {
                    *(float4*)(peer[q] + OFF_Z + gofs)     = vlo;
                    *(float4*)(peer[q] + OFF_Z + gofs + 4) = vhi;
                }
            }
        }
        cl.sync();   // prob (full) + Z (full) visible everywhere

        // ---- splice prob into A row/col i and the output ----
        if (tid < RPC) {
            const int jg = r0 + tid;
            if (jg < i) {
                const float pv = prob[jg];
                A[tid * NDIM + i] = pv;
                ob[(size_t)jg * NDIM + i] = pv;
            }
        }
        if (rank == (i >> 5) && tid < i) {
            const int il = i & 31;
            const float pv = prob[tid];
            A[il * NDIM + tid] = pv;
            ob[(size_t)i * NDIM + tid] = pv;
        }
        if (i == NDIM - 1) break;   // last step: only the splice matters
        __syncthreads();

        // ---- deg -> dinv (local rows), broadcast dinv ----
        {
            const int jl = tid >> 2, p = tid & 3;
            const float4* ar = (const float4*)(A + jl * NDIM) + (p << 3);
            float s = 0.f;
#pragma unroll
            for (int q = 0; q < 8; ++q) {
                const float4 u = ar[q];
                s += u.x + u.y + u.z + u.w;
            }
            s += __shfl_down_sync(0xffffffffu, s, 2);
            s += __shfl_down_sync(0xffffffffu, s, 1);
            if (p == 0) {
                float rv = rsqrtf(s);
                rv = rv * (1.5f - 0.5f * s * rv * rv);   // Newton refine
                const int jg = r0 + jl;
#pragma unroll
                for (int r = 0; r < CLUS; ++r)
                    peer[r][OFF_DINV + jg] = rv;
            }
        }
        cl.sync();   // dinv (full) visible

        // ---- A_local[r][c] *= dinv[r0+r] * dinv[c] ----
        for (int idx = tid; idx < 1024; idx += BLK) {
            const int lin = idx << 2;
            const int jr = lin >> 7, c4 = (lin & 127) >> 2;
            const float dr = dinv[r0 + jr];
            const float4 dc = ((const float4*)dinv)[c4];
            float4 v = ((float4*)A)[idx];
            v.x *= dr * dc.x; v.y *= dr * dc.y;
            v.z *= dr * dc.z; v.w *= dr * dc.w;
            ((float4*)A)[idx] = v;
        }
        __syncthreads();

        // ---- X_local = relu(A_local @ Z_full) ----
        {
            unsigned long long acc[4][4];
            gemm32_acc(A, Z, tr, tc, acc);
#pragma unroll
            for (int r = 0; r < 4; ++r) {
                *(float4*)(X + (tr + r) * NDIM + tc)     = acc_lo(acc[r], true);
                *(float4*)(X + (tr + r) * NDIM + tc + 4) = acc_hi(acc[r], true);
            }
        }
        __syncthreads();

        // ---- broadcast X row (i+1) from its owner for the next step ----
        {
            const int ni = i + 1;
            if (rank == (ni >> 5) && tid < 32) {
                const float4 v = ((const float4*)(X + (ni & 31) * NDIM))[tid];
#pragma unroll
                for (int r = 0; r < CLUS; ++r)
                    ((float4*)(peer[r] + OFF_XI))[tid] = v;
            }
        }
        cl.sync();
    }
}

extern "C" void kernel_launch(void* const* d_in, const int* in_sizes, int n_in,
                              void* d_out, int out_size)
{
    const float* x = (const float*)d_in[0];
    const float* W = (const float*)d_in[1];
    if (n_in >= 2 && in_sizes[0] == 16384 && in_sizes[1] != 16384) {
        const float* t = x; x = W; W = t;
    }
    float* out = (float*)d_out;

    const size_t smem_bytes = (size_t)SMEM_FLOATS * sizeof(float);  // 165376
    cudaFuncSetAttribute(gcn_kernel, cudaFuncAttributeMaxDynamicSharedMemorySize,
                         (int)smem_bytes);
    gcn_kernel<<<32 * CLUS, BLK, smem_bytes>>>(x, W, out);
}

// round 5
// speedup vs baseline: 1.6569x; 1.6569x over previous
#include <cuda_runtime.h>
#include <cooperative_groups.h>
namespace cg = cooperative_groups;

#define NDIM 128
#define RPC  32          // rows per CTA (quarter)
#define BLK  256         // 8 warps: 2/SMSP for latency hiding
#define CLUS 4

// shared-memory layout (float offsets)
#define OFF_W    0
#define OFF_Z    16384
#define OFF_A    32768          // 32x128 local quarter
#define OFF_X    36864          // 32x128 local quarter
#define OFF_XI   40960          // 128
#define OFF_PROB 41088          // 128
#define OFF_DINV 41216          // 128
#define SMEM_FLOATS 41344       // 165376 bytes

// ---------- packed f32x2 helpers ----------
__device__ __forceinline__ unsigned long long pack2(float v) {
    unsigned long long r;
    asm("mov.b64 %0, {%1, %1};" : "=l"(r) : "f"(v));
    return r;
}
__device__ __forceinline__ void fma2(unsigned long long& d, unsigned long long a, unsigned long long b) {
    asm("fma.rn.f32x2 %0, %1, %2, %0;" : "+l"(d) : "l"(a), "l"(b));
}
__device__ __forceinline__ float2 unpack2(unsigned long long v) {
    float2 r;
    asm("mov.b64 {%0, %1}, %2;" : "=f"(r.x), "=f"(r.y) : "l"(v));
    return r;
}
__device__ __forceinline__ float4 acc_f4(const unsigned long long a0,
                                         const unsigned long long a1, bool relu) {
    float2 lo = unpack2(a0), hi = unpack2(a1);
    float4 v = make_float4(lo.x, lo.y, hi.x, hi.y);
    if (relu) { v.x = fmaxf(v.x,0.f); v.y = fmaxf(v.y,0.f); v.z = fmaxf(v.z,0.f); v.w = fmaxf(v.w,0.f); }
    return v;
}

// ---------- 32xKbx128 GEMM accumulate: thread = 4 rows x 4 cols ----------
// 256 threads. Warp covers 2 row-groups x 16 contiguous col-groups (64 cols):
// B reads dedup to 256 B/warp/k -> crossbar 16 cyc/k vs FMA 32 cyc/k.
__device__ __forceinline__ void gemm_acc(const float* __restrict__ As,
                                         const float* __restrict__ Bs,
                                         int tr, int tc, int Kb,
                                         unsigned long long acc[4][2])
{
#pragma unroll
    for (int r = 0; r < 4; ++r) { acc[r][0] = 0ull; acc[r][1] = 0ull; }

#pragma unroll 2
    for (int k = 0; k < Kb; k += 4) {
        float4 a[4];
#pragma unroll
        for (int r = 0; r < 4; ++r)
            a[r] = *(const float4*)(As + (tr + r) * NDIM + k);
        ulonglong2 b[4];
#pragma unroll
        for (int kk = 0; kk < 4; ++kk)
            b[kk] = *(const ulonglong2*)(Bs + (k + kk) * NDIM + tc);
#pragma unroll
        for (int kk = 0; kk < 4; ++kk) {
#pragma unroll
            for (int r = 0; r < 4; ++r) {
                const unsigned long long p = pack2(((const float*)&a[r])[kk]);
                fma2(acc[r][0], p, b[kk].x);
                fma2(acc[r][1], p, b[kk].y);
            }
        }
    }
}

__global__ void __launch_bounds__(BLK, 1) __cluster_dims__(CLUS, 1, 1)
gcn_kernel(const float* __restrict__ xg, const float* __restrict__ Wg,
           float* __restrict__ outg)
{
    extern __shared__ float sm[];
    float* Ws   = sm + OFF_W;
    float* Z    = sm + OFF_Z;
    float* A    = sm + OFF_A;
    float* X    = sm + OFF_X;
    float* xi   = sm + OFF_XI;
    float* prob = sm + OFF_PROB;
    float* dinv = sm + OFF_DINV;

    cg::cluster_group cl = cg::this_cluster();
    const int rank  = (int)cl.block_rank();
    const int tid   = threadIdx.x;
    const int batch = blockIdx.x / CLUS;
    const int r0    = rank * RPC;

    // GEMM layout: warp covers 2 row-groups x one 64-col half (dedup B reads)
    const int w = tid >> 5, l = tid & 31;
    const int rg = ((w >> 1) << 1) | (l >> 4);         // 0..7
    const int cg = (l & 15) | ((w & 1) << 4);          // 0..31
    const int tr = rg << 2;                            // 0..28
    const int tc = cg << 2;                            // 0..124

    float* peer[CLUS];
#pragma unroll
    for (int r = 0; r < CLUS; ++r) peer[r] = (float*)cl.map_shared_rank((void*)sm, r);

    const float* __restrict__ xb = xg + (size_t)batch * 16384 + (size_t)r0 * NDIM;
    float* __restrict__ ob = outg + (size_t)batch * 16384;

    // ---- prologue: W -> smem, local x quarter -> Z[0..31], eye quarters ----
    for (int idx = tid; idx < 4096; idx += BLK)
        ((float4*)Ws)[idx] = ((const float4*)Wg)[idx];
    for (int idx = tid; idx < 1024; idx += BLK)
        ((float4*)Z)[idx] = ((const float4*)xb)[idx];
    for (int idx = tid; idx < 1024; idx += BLK) {
        const int lin = idx << 2;
        const int jg = r0 + (lin >> 7), c = lin & 127;
        float4 e = make_float4(0.f, 0.f, 0.f, 0.f);
        const int d = jg - c;
        if (d >= 0 && d < 4) ((float*)&e)[d] = 1.0f;
        ((float4*)(ob + (size_t)r0 * NDIM))[idx] = e;
        ((float4*)A)[idx] = e;
    }
    __syncthreads();

    // X_local = relu(x_local @ W)
    {
        unsigned long long acc[4][2];
        gemm_acc(Z, Ws, tr, tc, NDIM, acc);
#pragma unroll
        for (int r = 0; r < 4; ++r)
            *(float4*)(X + (tr + r) * NDIM + tc) = acc_f4(acc[r][0], acc[r][1], true);
    }
    __syncthreads();

    // broadcast X row 1 (owner: rank 0)
    if (rank == 0 && tid < 32) {
        const float4 v = ((const float4*)(X + 1 * NDIM))[tid];
#pragma unroll
        for (int r = 0; r < CLUS; ++r)
            ((float4*)(peer[r] + OFF_XI))[tid] = v;
    }
    cl.sync();

    for (int i = 1; i < NDIM; ++i) {
        // ---- prob[j] = dot(X_local[j], xi); broadcast. 8 threads per row ----
        {
            const int jl = tid >> 3, p = tid & 7;
            const float4* xj = (const float4*)(X + jl * NDIM) + (p << 2);
            const float4* xv = (const float4*)xi + (p << 2);
            float s = 0.f;
#pragma unroll
            for (int q = 0; q < 4; ++q) {
                const float4 u = xj[q], v = xv[q];
                s += u.x * v.x + u.y * v.y + u.z * v.z + u.w * v.w;
            }
            s += __shfl_down_sync(0xffffffffu, s, 4);
            s += __shfl_down_sync(0xffffffffu, s, 2);
            s += __shfl_down_sync(0xffffffffu, s, 1);
            if (p == 0) {
                const int jg = r0 + jl;
#pragma unroll
                for (int r = 0; r < CLUS; ++r)
                    peer[r][OFF_PROB + jg] = s;
            }
        }

        // ---- Z quarter = X_local @ W, scattered to every CTA's Z ----
        if (i < NDIM - 1) {
            unsigned long long acc[4][2];
            gemm_acc(X, Ws, tr, tc, NDIM, acc);
#pragma unroll
            for (int r = 0; r < 4; ++r) {
                const float4 v = acc_f4(acc[r][0], acc[r][1], false);
                const int gofs = (r0 + tr + r) * NDIM + tc;
#pragma unroll
                for (int q = 0; q < CLUS; ++q)
                    *(float4*)(peer[q] + OFF_Z + gofs) = v;
            }
        }
        cl.sync();   // prob + Z visible everywhere

        // ---- splice prob into A row/col i and the output ----
        if (tid < RPC) {
            const int jg = r0 + tid;
            if (jg < i) {
                const float pv = prob[jg];
                A[tid * NDIM + i] = pv;
                ob[(size_t)jg * NDIM + i] = pv;
            }
        }
        if (rank == (i >> 5) && tid < i) {
            const int il = i & 31;
            const float pv = prob[tid];
            A[il * NDIM + tid] = pv;
            ob[(size_t)i * NDIM + tid] = pv;
        }
        if (i == NDIM - 1) break;
        __syncthreads();

        // ---- deg -> dinv (local rows), broadcast ----
        {
            const int jl = tid >> 3, p = tid & 7;
            const float4* ar = (const float4*)(A + jl * NDIM) + (p << 2);
            float s = 0.f;
#pragma unroll
            for (int q = 0; q < 4; ++q) {
                const float4 u = ar[q];
                s += u.x + u.y + u.z + u.w;
            }
            s += __shfl_down_sync(0xffffffffu, s, 4);
            s += __shfl_down_sync(0xffffffffu, s, 2);
            s += __shfl_down_sync(0xffffffffu, s, 1);
            if (p == 0) {
                float rv = rsqrtf(s);
                rv = rv * (1.5f - 0.5f * s * rv * rv);
                const int jg = r0 + jl;
#pragma unroll
                for (int r = 0; r < CLUS; ++r)
                    peer[r][OFF_DINV + jg] = rv;
            }
        }
        cl.sync();   // dinv visible

        // ---- A_local[r][c] *= dinv[r0+r] * dinv[c] ----
        for (int idx = tid; idx < 1024; idx += BLK) {
            const int lin = idx << 2;
            const int jr = lin >> 7, c4 = (lin & 127) >> 2;
            const float dr = dinv[r0 + jr];
            const float4 dc = ((const float4*)dinv)[c4];
            float4 v = ((float4*)A)[idx];
            v.x *= dr * dc.x; v.y *= dr * dc.y;
            v.z *= dr * dc.z; v.w *= dr * dc.w;
            ((float4*)A)[idx] = v;
        }
        __syncthreads();

        // ---- X_local = relu(A_local @ Z), exploiting triangular structure:
        //      cols > i of A are zero except the diagonal; rows gr >= Kb
        //      reduce to relu(Z[gr]).  Kb = roundup(i+1, 4).
        {
            int Kb = (i + 4) & ~3;
            if (Kb > NDIM) Kb = NDIM;
            unsigned long long acc[4][2];
            if (r0 < Kb) gemm_acc(A, Z, tr, tc, Kb, acc);
#pragma unroll
            for (int r = 0; r < 4; ++r) {
                const int gr = r0 + tr + r;
                float4 v;
                if (gr < Kb) {
                    v = acc_f4(acc[r][0], acc[r][1], true);
                } else {
                    v = *(const float4*)(Z + gr * NDIM + tc);
                    v.x = fmaxf(v.x, 0.f); v.y = fmaxf(v.y, 0.f);
                    v.z = fmaxf(v.z, 0.f); v.w = fmaxf(v.w, 0.f);
                }
                *(float4*)(X + (tr + r) * NDIM + tc) = v;
            }
        }
        __syncthreads();

        // ---- broadcast X row (i+1) from its owner ----
        {
            const int ni = i + 1;
            if (rank == (ni >> 5) && tid < 32) {
                const float4 v = ((const float4*)(X + (ni & 31) * NDIM))[tid];
#pragma unroll
                for (int r = 0; r < CLUS; ++r)
                    ((float4*)(peer[r] + OFF_XI))[tid] = v;
            }
        }
        cl.sync();
    }
}

extern "C" void kernel_launch(void* const* d_in, const int* in_sizes, int n_in,
                              void* d_out, int out_size)
{
    const float* x = (const float*)d_in[0];
    const float* W = (const float*)d_in[1];
    if (n_in >= 2 && in_sizes[0] == 16384 && in_sizes[1] != 16384) {
        const float* t = x; x = W; W = t;
    }
    float* out = (float*)d_out;

    const size_t smem_bytes = (size_t)SMEM_FLOATS * sizeof(float);  // 165376
    cudaFuncSetAttribute(gcn_kernel, cudaFuncAttributeMaxDynamicSharedMemorySize,
                         (int)smem_bytes);
    gcn_kernel<<<32 * CLUS, BLK, smem_bytes>>>(x, W, out);
}

// round 6
// speedup vs baseline: 1.9177x; 1.1574x over previous
#include <cuda_runtime.h>
#include <cooperative_groups.h>
namespace cg = cooperative_groups;

#define NDIM 128
#define BLK  256         // 8 warps
#define CLUS 4

// shared-memory layout (float offsets)
#define OFF_W    0              // 16384
#define OFF_Z    16384          // 16384 (full Z, global-row indexed)
#define OFF_A    32768          // 32x128 local rows (interleaved ownership)
#define OFF_X    36864          // 32x128 local rows
#define OFF_XI   40960          // 128
#define OFF_PROB 41088          // 128
#define OFF_DINV 41216          // 128
#define OFF_RS   41344          // 2 x 128 (parity double buffer)
#define OFF_RED  41600          // 8
#define SMEM_FLOATS 41616       // 166464 bytes

// ---------- packed f32x2 helpers ----------
__device__ __forceinline__ unsigned long long pack2(float v) {
    unsigned long long r;
    asm("mov.b64 %0, {%1, %1};" : "=l"(r) : "f"(v));
    return r;
}
__device__ __forceinline__ void fma2(unsigned long long& d, unsigned long long a, unsigned long long b) {
    asm("fma.rn.f32x2 %0, %1, %2, %0;" : "+l"(d) : "l"(a), "l"(b));
}
__device__ __forceinline__ float2 unpack2(unsigned long long v) {
    float2 r;
    asm("mov.b64 {%0, %1}, %2;" : "=f"(r.x), "=f"(r.y) : "l"(v));
    return r;
}
__device__ __forceinline__ float4 acc_f4(const unsigned long long a0,
                                         const unsigned long long a1, bool relu) {
    float2 lo = unpack2(a0), hi = unpack2(a1);
    float4 v = make_float4(lo.x, lo.y, hi.x, hi.y);
    if (relu) { v.x = fmaxf(v.x,0.f); v.y = fmaxf(v.y,0.f); v.z = fmaxf(v.z,0.f); v.w = fmaxf(v.w,0.f); }
    return v;
}

// ---------- 32(local rows) x 128 x Kb GEMM: thread = 4 rows x 4 cols ----------
// 256 threads. Warp = 2 row-groups x 16 col-groups over one 64-col half:
// B reads dedup to 256B/warp/k.
__device__ __forceinline__ void gemm_acc(const float* __restrict__ As,
                                         const float* __restrict__ Bs,
                                         int tr, int tc, int Kb,
                                         unsigned long long acc[4][2])
{
#pragma unroll
    for (int r = 0; r < 4; ++r) { acc[r][0] = 0ull; acc[r][1] = 0ull; }

#pragma unroll 2
    for (int k = 0; k < Kb; k += 4) {
        float4 a[4];
#pragma unroll
        for (int r = 0; r < 4; ++r)
            a[r] = *(const float4*)(As + (tr + r) * NDIM + k);
        ulonglong2 b[4];
#pragma unroll
        for (int kk = 0; kk < 4; ++kk)
            b[kk] = *(const ulonglong2*)(Bs + (k + kk) * NDIM + tc);
#pragma unroll
        for (int kk = 0; kk < 4; ++kk) {
#pragma unroll
            for (int r = 0; r < 4; ++r) {
                const unsigned long long p = pack2(((const float*)&a[r])[kk]);
                fma2(acc[r][0], p, b[kk].x);
                fma2(acc[r][1], p, b[kk].y);
            }
        }
    }
}

__global__ void __launch_bounds__(BLK, 1) __cluster_dims__(CLUS, 1, 1)
gcn_kernel(const float* __restrict__ xg, const float* __restrict__ Wg,
           float* __restrict__ outg)
{
    extern __shared__ float sm[];
    float* Ws   = sm + OFF_W;
    float* Z    = sm + OFF_Z;
    float* A    = sm + OFF_A;
    float* X    = sm + OFF_X;
    float* xi   = sm + OFF_XI;
    float* prob = sm + OFF_PROB;
    float* dinv = sm + OFF_DINV;
    float* red  = sm + OFF_RED;

    cg::cluster_group cl = cg::this_cluster();
    const int rank  = (int)cl.block_rank();
    const int tid   = threadIdx.x;
    const int batch = blockIdx.x / CLUS;

    // interleaved ownership: local row jl <-> global row g = 4*jl + rank
    const int w = tid >> 5, l = tid & 31;
    const int rg = ((w >> 1) << 1) | (l >> 4);         // 0..7
    const int cgp = (l & 15) | ((w & 1) << 4);         // 0..31
    const int tr = rg << 2;                            // 0..28 (local rows)
    const int tc = cgp << 2;                           // 0..124

    float* peer[CLUS];
#pragma unroll
    for (int r = 0; r < CLUS; ++r) peer[r] = (float*)cl.map_shared_rank((void*)sm, r);

    const float* __restrict__ xb = xg + (size_t)batch * 16384;
    float* __restrict__ ob = outg + (size_t)batch * 16384;

    // ---- prologue ----
    for (int idx = tid; idx < 4096; idx += BLK)
        ((float4*)Ws)[idx] = ((const float4*)Wg)[idx];
    for (int idx = tid; idx < 1024; idx += BLK) {           // local x rows -> Z temp
        const int jl = idx >> 5, c4 = idx & 31;
        const int g = (jl << 2) | rank;
        ((float4*)(Z + jl * NDIM))[c4] = ((const float4*)(xb + (size_t)g * NDIM))[c4];
    }
    for (int idx = tid; idx < 1024; idx += BLK) {           // eye quarters
        const int jl = idx >> 5, c4 = idx & 31;
        const int g = (jl << 2) | rank;
        float4 e = make_float4(0.f, 0.f, 0.f, 0.f);
        const int d = g - (c4 << 2);
        if (d >= 0 && d < 4) ((float*)&e)[d] = 1.0f;
        ((float4*)(A + jl * NDIM))[c4] = e;
        ((float4*)(ob + (size_t)g * NDIM))[c4] = e;
    }
    if (tid < NDIM) sm[OFF_RS + NDIM + tid] = 1.0f;         // rs parity buf for i=1
    __syncthreads();

    // X_local = relu(x_local @ W)
    {
        unsigned long long acc[4][2];
        gemm_acc(Z, Ws, tr, tc, NDIM, acc);
#pragma unroll
        for (int r = 0; r < 4; ++r)
            *(float4*)(X + (tr + r) * NDIM + tc) = acc_f4(acc[r][0], acc[r][1], true);
    }
    __syncthreads();

    // broadcast X row 1 (global row 1 => rank 1, jl 0)
    if (rank == 1 && tid < 32) {
        const float4 v = ((const float4*)X)[tid];
#pragma unroll
        for (int r = 0; r < CLUS; ++r)
            ((float4*)(peer[r] + OFF_XI))[tid] = v;
    }
    cl.sync();

    for (int i = 1; i < NDIM; ++i) {
        int Kb = (i + 4) & ~3;
        if (Kb > NDIM) Kb = NDIM;

        // ---- prob[g] = dot(X_local[jl], xi); scatter ----
        {
            const int jl = tid >> 3, p = tid & 7;
            const float4* xj = (const float4*)(X + jl * NDIM) + (p << 2);
            const float4* xv = (const float4*)xi + (p << 2);
            float s = 0.f;
#pragma unroll
            for (int q = 0; q < 4; ++q) {
                const float4 u = xj[q], v = xv[q];
                s += u.x * v.x + u.y * v.y + u.z * v.z + u.w * v.w;
            }
            s += __shfl_down_sync(0xffffffffu, s, 4);
            s += __shfl_down_sync(0xffffffffu, s, 2);
            s += __shfl_down_sync(0xffffffffu, s, 1);
            if (p == 0) {
                const int g = (jl << 2) | rank;
#pragma unroll
                for (int r = 0; r < CLUS; ++r)
                    peer[r][OFF_PROB + g] = s;
            }
        }

        // ---- Z = X_local @ W; local always, remote only rows g < Kb ----
        if (i < NDIM - 1) {
            unsigned long long acc[4][2];
            gemm_acc(X, Ws, tr, tc, NDIM, acc);
#pragma unroll
            for (int r = 0; r < 4; ++r) {
                const float4 v = acc_f4(acc[r][0], acc[r][1], false);
                const int g = ((tr + r) << 2) | rank;
                *(float4*)(Z + g * NDIM + tc) = v;
                if (g < Kb) {
#pragma unroll
                    for (int q = 0; q < CLUS; ++q)
                        if (q != rank)
                            *(float4*)(peer[q] + OFF_Z + g * NDIM + tc) = v;
                }
            }
        }
        cl.sync();   // prob + Z visible everywhere

        // ---- partial reduce of sum_{j<i} prob[j] ----
        {
            float ps = (tid < i) ? prob[tid] : 0.f;   // tid>=128 => 0
            ps += __shfl_down_sync(0xffffffffu, ps, 16);
            ps += __shfl_down_sync(0xffffffffu, ps, 8);
            ps += __shfl_down_sync(0xffffffffu, ps, 4);
            ps += __shfl_down_sync(0xffffffffu, ps, 2);
            ps += __shfl_down_sync(0xffffffffu, ps, 1);
            if (l == 0) red[w] = ps;
        }
        // ---- splice col i into local A rows + output ----
        if (tid < 32) {
            const int jl = tid, g = (jl << 2) | rank;
            if (g < i) {
                const float pv = prob[g];
                A[jl * NDIM + i] = pv;
                ob[(size_t)g * NDIM + i] = pv;
            }
        }
        // ---- splice row i (owner) + output ----
        if (rank == (i & 3) && tid < i) {
            const int il = i >> 2;
            const float pv = prob[tid];
            A[il * NDIM + tid] = pv;
            ob[(size_t)i * NDIM + tid] = pv;
        }
        if (i == NDIM - 1) break;
        __syncthreads();

        // ---- full dinv computed locally by every CTA (no exchange) ----
        if (tid < NDIM) {
            const float sp = red[0] + red[1] + red[2] + red[3]
                           + red[4] + red[5] + red[6] + red[7];
            float dg = sm[OFF_RS + ((i & 1) << 7) + tid];
            if (tid < i)       dg += prob[tid];
            else if (tid == i) dg += sp;
            float rv = rsqrtf(dg);
            rv = rv * (1.5f - 0.5f * dg * rv * rv);   // Newton refine
            dinv[tid] = rv;
        }
        __syncthreads();

        // ---- normalize local A rows; accumulate rs_next; scatter rs ----
        {
            const int jl = tid >> 3, p = tid & 7;
            const int g = (jl << 2) | rank;
            const float dr = dinv[g];
            float* arow = A + jl * NDIM;
            float s = 0.f;
#pragma unroll
            for (int q = 0; q < 4; ++q) {
                const int c4 = p + (q << 3);
                const float4 dc = ((const float4*)dinv)[c4];
                float4 v = ((float4*)arow)[c4];
                v.x *= dr * dc.x; v.y *= dr * dc.y;
                v.z *= dr * dc.z; v.w *= dr * dc.w;
                ((float4*)arow)[c4] = v;
                s += v.x + v.y + v.z + v.w;
            }
            s += __shfl_down_sync(0xffffffffu, s, 4);
            s += __shfl_down_sync(0xffffffffu, s, 2);
            s += __shfl_down_sync(0xffffffffu, s, 1);
            if (p == 0) {
                const int dst = OFF_RS + (((i & 1) ^ 1) << 7) + g;
#pragma unroll
                for (int r = 0; r < CLUS; ++r)
                    peer[r][dst] = s;
            }
        }
        __syncthreads();

        // ---- X_local = relu(A_local @ Z) for rows g<Kb, else relu(Z[g]) ----
        {
            const int m = Kb >> 2;    // active local rows per CTA
            unsigned long long acc[4][2];
            if (tr < m) gemm_acc(A, Z, tr, tc, Kb, acc);
#pragma unroll
            for (int r = 0; r < 4; ++r) {
                const int jl = tr + r, g = (jl << 2) | rank;
                float4 v;
                if (jl < m) {
                    v = acc_f4(acc[r][0], acc[r][1], true);
                } else {
                    v = *(const float4*)(Z + g * NDIM + tc);
                    v.x = fmaxf(v.x, 0.f); v.y = fmaxf(v.y, 0.f);
                    v.z = fmaxf(v.z, 0.f); v.w = fmaxf(v.w, 0.f);
                }
                *(float4*)(X + jl * NDIM + tc) = v;
            }
        }
        __syncthreads();

        // ---- broadcast X row (i+1) from its owner ----
        {
            const int ni = i + 1;
            if (rank == (ni & 3) && tid < 32) {
                const float4 v = ((const float4*)(X + (ni >> 2) * NDIM))[tid];
#pragma unroll
                for (int r = 0; r < CLUS; ++r)
                    ((float4*)(peer[r] + OFF_XI))[tid] = v;
            }
        }
        cl.sync();   // rs + xi + X visible; Z free for next iter
    }
}

extern "C" void kernel_launch(void* const* d_in, const int* in_sizes, int n_in,
                              void* d_out, int out_size)
{
    const float* x = (const float*)d_in[0];
    const float* W = (const float*)d_in[1];
    if (n_in >= 2 && in_sizes[0] == 16384 && in_sizes[1] != 16384) {
        const float* t = x; x = W; W = t;
    }
    float* out = (float*)d_out;

    const size_t smem_bytes = (size_t)SMEM_FLOATS * sizeof(float);  // 166464
    cudaFuncSetAttribute(gcn_kernel, cudaFuncAttributeMaxDynamicSharedMemorySize,
                         (int)smem_bytes);
    gcn_kernel<<<32 * CLUS, BLK, smem_bytes>>>(x, W, out);
}